// round 13
// baseline (speedup 1.0000x reference)
#include <cuda_runtime.h>
#include <cuda_bf16.h>
#include <math.h>

// Problem constants (fixed by the reference)
#define BN    8192
#define CN    2048
#define LN    6
#define HALF  4096
#define MN    (BN + LN)          // 8198
#define XOUT_ELEMS ((size_t)MN * CN)
#define ADJ_OFF    XOUT_ELEMS

#define G     4                  // rows staged per group
#define NGRP  16                 // groups per block (64 rows/block, grid 128)
#define NPASS 128

// ---- scratch (no allocations; zero-init at load; finisher re-zeroes so
//      every graph replay sees zeros — validated pattern from R11) ----
__device__ float    g_U[LN * CN];
__device__ float    g_denom[LN];
__device__ float    g_cnt[LN];
__device__ unsigned g_done;

// ---------------------------------------------------------------------------
// 1) pass (R12 512-thread body, unchanged) + fused zero/tail via the
//    validated last-block ticket: ONE kernel node for the whole main chain.
// ---------------------------------------------------------------------------
__global__ void __launch_bounds__(512) pass_kernel(
    const float* __restrict__ x, const int* __restrict__ cams,
    const float* __restrict__ att_w, const float* __restrict__ att_b,
    const float* __restrict__ rmean, float* __restrict__ out)
{
    __shared__ float sx[G][CN];      // 32 KB staged rows
    __shared__ float sscore[G];
    __shared__ int   scam[G];
    __shared__ float sden[LN];
    __shared__ float scnt[LN];
    __shared__ int   sIsLast;

    const int t = threadIdx.x;
    const int w = t >> 5, lane = t & 31;
    if (t < LN) { sden[t] = 0.0f; scnt[t] = 0.0f; }

    float acc[LN][4];
#pragma unroll
    for (int l = 0; l < LN; ++l)
#pragma unroll
        for (int k = 0; k < 4; ++k) acc[l][k] = 0.0f;

    const int r0 = blockIdx.x * (G * NGRP);          // 64 rows per block
    const float4* __restrict__ x4 = (const float4*)x;
    const float4* __restrict__ w4 = (const float4*)att_w;
    float4* __restrict__ o4 = (float4*)out;

    // preload group 0 (4 float4 per thread; row = f>>9, col4 = f&511)
    float4 buf[4];
#pragma unroll
    for (int m = 0; m < 4; ++m) {
        const int f = t + 512 * m;
        buf[m] = x4[(size_t)(r0 + (f >> 9)) * 512 + (f & 511)];
    }

    for (int g = 0; g < NGRP; ++g) {
        const int rows = r0 + G * g;

        __syncthreads();   // smem free (prev accumulate done; sden init on g=0)

        // stage to smem + fused copy to out
#pragma unroll
        for (int m = 0; m < 4; ++m) {
            const int f = t + 512 * m;
            const int rig = f >> 9, c4 = f & 511;
            *(float4*)&sx[rig][4 * c4] = buf[m];
            o4[(size_t)(rows + rig) * 512 + c4] = buf[m];
        }
        if (t < G) scam[t] = __ldg(&cams[rows + t]);
        __syncthreads();

        // score: warp w scores row w (w < G)
        if (w < G) {
            const int cam = scam[w];
            float s = 0.0f;
#pragma unroll
            for (int k = 0; k < 16; ++k) {
                const int c4 = lane + 32 * k;
                const float4 xv = *(const float4*)&sx[w][4 * c4];
                const float4 wv = __ldg(&w4[(size_t)cam * 512 + c4]);
                s += xv.x * wv.x + xv.y * wv.y + xv.z * wv.z + xv.w * wv.w;
            }
#pragma unroll
            for (int o = 16; o > 0; o >>= 1) s += __shfl_down_sync(0xffffffffu, s, o);
            if (lane == 0) {
                s += __ldg(&att_b[cam]);
                sscore[w] = s;
                atomicAdd(&sden[cam], s);
                atomicAdd(&scnt[cam], 1.0f);
            }
        }
        __syncthreads();

        // issue next group's global loads BEFORE the accumulate (overlap)
        if (g + 1 < NGRP) {
#pragma unroll
            for (int m = 0; m < 4; ++m) {
                const int f = t + 512 * m;
                buf[m] = x4[(size_t)(rows + G + (f >> 9)) * 512 + (f & 511)];
            }
        }

        // accumulate: 4 rows x 4 owned cols
#pragma unroll
        for (int r = 0; r < G; ++r) {
            const float s = sscore[r];
            const int cam = scam[r];
            const float4 xa = *(const float4*)&sx[r][4 * t];
#pragma unroll
            for (int l = 0; l < LN; ++l) {
                const float sl = (cam == l) ? s : 0.0f;
                acc[l][0] += sl * xa.x;  acc[l][1] += sl * xa.y;
                acc[l][2] += sl * xa.z;  acc[l][3] += sl * xa.w;
            }
        }
    }

    // flush partials (4 owned columns per thread)
#pragma unroll
    for (int l = 0; l < LN; ++l)
#pragma unroll
        for (int k = 0; k < 4; ++k)
            atomicAdd(&g_U[l * CN + 4 * t + k], acc[l][k]);
    if (t < LN) {
        atomicAdd(&g_denom[t], sden[t]);
        atomicAdd(&g_cnt[t],   scnt[t]);
    }

    // ---- last-block tail + scratch reset (validated R11 pattern) ----
    __threadfence();
    __syncthreads();
    if (t == 0)
        sIsLast = (atomicAdd(&g_done, 1u) == NPASS - 1);
    __syncthreads();

    if (sIsLast) {
        __threadfence();
        float den[LN], cnt[LN];
#pragma unroll
        for (int l = 0; l < LN; ++l) {
            den[l] = __ldcg(&g_denom[l]);
            cnt[l] = __ldcg(&g_cnt[l]);
        }
#pragma unroll 4
        for (int idx = t; idx < LN * CN; idx += 512) {
            const int l = idx >> 11;
            const float u = __ldcg(&g_U[idx]);
            const float v = (cnt[l] > 0.0f) ? (u / den[l]) : __ldg(&rmean[idx]);
            out[(size_t)BN * CN + idx] = v;
            g_U[idx] = 0.0f;                 // reset for next replay
        }
        if (t < LN) { g_denom[t] = 0.0f; g_cnt[t] = 0.0f; }
        __syncthreads();
        if (t == 0) g_done = 0u;
    }
}

// ---------------------------------------------------------------------------
// 2) adj fill (FROZEN — ~41us @ 63% DRAM): pure constant segmented fill.
// ---------------------------------------------------------------------------
__global__ void __launch_bounds__(256) adj_kernel(float* __restrict__ out)
{
    const int i = blockIdx.x;
    const int t = threadIdx.x;

    const float DA = rsqrtf(4098.0f);   // rgb sample
    const float DB = rsqrtf(4100.0f);   // ir sample
    const float DC = rsqrtf(4097.0f);   // cam node

    float lo, hi;                       // cols [0,4096) / [4096,8192)
    if (i < HALF)        { lo = DA * DA; hi = 0.0f;    }
    else if (i < BN)     { lo = 0.0f;    hi = DB * DB; }
    else if (i < BN + 4) { lo = 0.0f;    hi = DC * DB; }
    else                 { lo = DC * DA; hi = 0.0f;    }

    float2* row = (float2*)(out + ADJ_OFF + (size_t)i * MN);
    const float2 lo2 = make_float2(lo, lo);
    const float2 hi2 = make_float2(hi, hi);

#pragma unroll
    for (int k = 0; k < 8; ++k) __stcs(&row[t + 256 * k], lo2);
#pragma unroll
    for (int k = 0; k < 8; ++k) __stcs(&row[2048 + t + 256 * k], hi2);

    if (t < 3) {
        float2 tp = make_float2(0.0f, 0.0f);
        if (i < HALF) {
            if (t == 2) tp = make_float2(DA * DC, DA * DC);
        } else if (i < BN) {
            if (t < 2) tp = make_float2(DB * DC, DB * DC);
        } else {
            const int l = i - BN;
            if ((l >> 1) == t) {
                if (l & 1) tp.y = DC * DC; else tp.x = DC * DC;
            }
        }
        __stcs(&row[4096 + t], tp);
    }
}

// ---------------------------------------------------------------------------
// Launch: TWO kernel nodes total. pass (with fused zero/tail) on the main
// stream; adj forked onto a least-priority stream; join at the end.
// ---------------------------------------------------------------------------
extern "C" void kernel_launch(void* const* d_in, const int* in_sizes, int n_in,
                              void* d_out, int out_size)
{
    const float* x = nullptr; const int* cams = nullptr;
    const float* att_w = nullptr; const float* att_b = nullptr;
    const float* rmean = nullptr;

    for (int i = 0; i < n_in; ++i) {
        const int sz = in_sizes[i];
        if      (sz == BN * CN)           x = (const float*)d_in[i];
        else if (sz == BN)                cams = (const int*)d_in[i];
        else if (sz == LN * CN) { if (!att_w) att_w = (const float*)d_in[i];
                                  else        rmean = (const float*)d_in[i]; }
        else if (sz == LN)                att_b = (const float*)d_in[i];
    }

    float* out = (float*)d_out;

    static cudaStream_t s2 = nullptr;
    static cudaEvent_t evFork = nullptr, evJoin = nullptr;
    if (s2 == nullptr) {
        int loPri = 0, hiPri = 0;
        cudaDeviceGetStreamPriorityRange(&loPri, &hiPri);
        cudaStreamCreateWithPriority(&s2, cudaStreamNonBlocking, loPri);
        cudaEventCreateWithFlags(&evFork, cudaEventDisableTiming);
        cudaEventCreateWithFlags(&evJoin, cudaEventDisableTiming);
    }

    cudaEventRecord(evFork, 0);

    pass_kernel<<<NPASS, 512>>>(x, cams, att_w, att_b, rmean, out);

    cudaStreamWaitEvent(s2, evFork, 0);
    adj_kernel<<<MN, 256, 0, s2>>>(out);
    cudaEventRecord(evJoin, s2);

    cudaStreamWaitEvent(0, evJoin, 0);
}

// round 14
// speedup vs baseline: 1.0216x; 1.0216x over previous
#include <cuda_runtime.h>
#include <cuda_bf16.h>
#include <math.h>

// Problem constants (fixed by the reference)
#define BN    8192
#define CN    2048
#define LN    6
#define HALF  4096
#define MN    (BN + LN)          // 8198
#define XOUT_ELEMS ((size_t)MN * CN)
#define ADJ_OFF    XOUT_ELEMS

#define RPB   32                 // rows per pass block
#define NPB   (BN / RPB)         // 256 pass blocks

// ---- scratch (no allocations allowed) ----
__device__ float g_U[LN * CN];   // sum_n s_n * x_n per cam
__device__ float g_denom[LN];    // per-cam sum of scores
__device__ float g_cnt[LN];      // per-cam counts

// ---------------------------------------------------------------------------
// 0) zero the scratch accumulators (graph replays reuse them)
// ---------------------------------------------------------------------------
__global__ void zero_kernel() {
    int idx = blockIdx.x * blockDim.x + threadIdx.x;
    if (idx < LN * CN) g_U[idx] = 0.0f;
    if (idx < LN) { g_denom[idx] = 0.0f; g_cnt[idx] = 0.0f; }
}

// ---------------------------------------------------------------------------
// 1) pass: ONE __syncthreads per block (was 32+).
//    Phase 1: warp-autonomous scoring — warp w scores rows 4w..4w+3
//             (coalesced x read + fused copy to out + L1-resident w dot +
//              shfl reduce). No block barriers.
//    Phase 2: thread t owns cols [4t,4t+4) and [1024+4t,+4); re-reads the
//             block's 32 rows from L2 (hot — streamed moments ago) with
//             next-row prefetch, accumulating acc[NC][8] in registers.
//    Template [CB,CB+NC): blocks <128 carry rows <4096 (cams 0..3);
//    blocks >=128 carry rows >=4096 (cams 4..5) — fixed batch layout.
// ---------------------------------------------------------------------------
template<int CB, int NC>
__device__ __forceinline__ void pass_body(
    const float* __restrict__ x, const int* __restrict__ cams,
    const float* __restrict__ att_w, const float* __restrict__ att_b,
    float* __restrict__ out, int rowBase)
{
    __shared__ float sscore[RPB];
    __shared__ int   scam[RPB];
    __shared__ float sden[LN];
    __shared__ float scnt[LN];

    const int t = threadIdx.x;
    const int w = t >> 5, lane = t & 31;
    if (t < LN) { sden[t] = 0.0f; scnt[t] = 0.0f; }
    __syncthreads();   // sden ready before phase-1 atomics

    const float4* __restrict__ x4 = (const float4*)x;
    const float4* __restrict__ w4 = (const float4*)att_w;
    float4* __restrict__ o4 = (float4*)out;

    // ---- phase 1: score 4 rows per warp, copy x -> out ----
    for (int rr = 0; rr < 4; ++rr) {
        const int rl = 4 * w + rr;            // 0..31
        const int r  = rowBase + rl;
        const int cam = __ldg(&cams[r]);
        float dot = 0.0f;
#pragma unroll
        for (int k = 0; k < 16; ++k) {
            const int c4 = lane + 32 * k;
            const float4 xv = x4[(size_t)r * 512 + c4];
            const float4 wv = __ldg(&w4[(size_t)cam * 512 + c4]);
            dot += xv.x * wv.x + xv.y * wv.y + xv.z * wv.z + xv.w * wv.w;
            o4[(size_t)r * 512 + c4] = xv;
        }
#pragma unroll
        for (int o = 16; o > 0; o >>= 1) dot += __shfl_xor_sync(0xffffffffu, dot, o);
        if (lane == 0) {
            const float s = dot + __ldg(&att_b[cam]);
            sscore[rl] = s;
            scam[rl]   = cam;
            atomicAdd(&sden[cam], s);
            atomicAdd(&scnt[cam], 1.0f);
        }
    }
    __syncthreads();   // the ONLY block-wide phase barrier

    // ---- phase 2: column-owned accumulation over the block's rows (L2) ----
    float acc[NC][8];
#pragma unroll
    for (int l = 0; l < NC; ++l)
#pragma unroll
        for (int k = 0; k < 8; ++k) acc[l][k] = 0.0f;

    const float4* __restrict__ xr = x4 + (size_t)rowBase * 512;
    float4 xa = xr[t];
    float4 xb = xr[256 + t];

    for (int r = 0; r < RPB; ++r) {
        float4 na, nb;
        if (r + 1 < RPB) {                    // prefetch next row (L2 hit)
            na = xr[(size_t)(r + 1) * 512 + t];
            nb = xr[(size_t)(r + 1) * 512 + 256 + t];
        }
        const float s = sscore[r];
        int ci = scam[r] - CB;
        ci = (ci < 0) ? 0 : (ci >= NC ? NC - 1 : ci);   // safety clamp
#pragma unroll
        for (int l = 0; l < NC; ++l) {
            const float sl = (ci == l) ? s : 0.0f;
            acc[l][0] += sl * xa.x;  acc[l][1] += sl * xa.y;
            acc[l][2] += sl * xa.z;  acc[l][3] += sl * xa.w;
            acc[l][4] += sl * xb.x;  acc[l][5] += sl * xb.y;
            acc[l][6] += sl * xb.z;  acc[l][7] += sl * xb.w;
        }
        xa = na; xb = nb;
    }

    // flush partials (spread atomics — validated pattern)
#pragma unroll
    for (int l = 0; l < NC; ++l) {
#pragma unroll
        for (int k = 0; k < 4; ++k)
            atomicAdd(&g_U[(CB + l) * CN + 4 * t + k], acc[l][k]);
#pragma unroll
        for (int k = 0; k < 4; ++k)
            atomicAdd(&g_U[(CB + l) * CN + 1024 + 4 * t + k], acc[l][k + 4]);
    }
    if (t < LN) {
        atomicAdd(&g_denom[t], sden[t]);
        atomicAdd(&g_cnt[t],   scnt[t]);
    }
}

__global__ void __launch_bounds__(256) pass_kernel(
    const float* __restrict__ x, const int* __restrict__ cams,
    const float* __restrict__ att_w, const float* __restrict__ att_b,
    float* __restrict__ out)
{
    const int b = blockIdx.x;
    if (b < NPB / 2) pass_body<0, 4>(x, cams, att_w, att_b, out, b * RPB);
    else             pass_body<4, 2>(x, cams, att_w, att_b, out, b * RPB);
}

// ---------------------------------------------------------------------------
// 2) tail rows of x_out:  U/denom if cam present, else running_mean
// ---------------------------------------------------------------------------
__global__ void tail_kernel(const float* __restrict__ rmean,
                            float* __restrict__ out)
{
    int idx = blockIdx.x * blockDim.x + threadIdx.x;
    if (idx < LN * CN) {
        int l = idx >> 11;
        float v = (g_cnt[l] > 0.0f) ? (g_U[idx] / g_denom[l]) : __ldg(&rmean[idx]);
        out[(size_t)BN * CN + idx] = v;
    }
}

// ---------------------------------------------------------------------------
// 3) adj fill (FROZEN — ~41us @ 63% DRAM): pure constant segmented fill;
//    rowsums pinned by the fixed batch layout.
// ---------------------------------------------------------------------------
__global__ void __launch_bounds__(256) adj_kernel(float* __restrict__ out)
{
    const int i = blockIdx.x;
    const int t = threadIdx.x;

    const float DA = rsqrtf(4098.0f);   // rgb sample
    const float DB = rsqrtf(4100.0f);   // ir sample
    const float DC = rsqrtf(4097.0f);   // cam node

    float lo, hi;                       // cols [0,4096) / [4096,8192)
    if (i < HALF)        { lo = DA * DA; hi = 0.0f;    }
    else if (i < BN)     { lo = 0.0f;    hi = DB * DB; }
    else if (i < BN + 4) { lo = 0.0f;    hi = DC * DB; }
    else                 { lo = DC * DA; hi = 0.0f;    }

    float2* row = (float2*)(out + ADJ_OFF + (size_t)i * MN);
    const float2 lo2 = make_float2(lo, lo);
    const float2 hi2 = make_float2(hi, hi);

#pragma unroll
    for (int k = 0; k < 8; ++k) __stcs(&row[t + 256 * k], lo2);
#pragma unroll
    for (int k = 0; k < 8; ++k) __stcs(&row[2048 + t + 256 * k], hi2);

    if (t < 3) {
        float2 tp = make_float2(0.0f, 0.0f);
        if (i < HALF) {
            if (t == 2) tp = make_float2(DA * DC, DA * DC);
        } else if (i < BN) {
            if (t < 2) tp = make_float2(DB * DC, DB * DC);
        } else {
            const int l = i - BN;
            if ((l >> 1) == t) {
                if (l & 1) tp.y = DC * DC; else tp.x = DC * DC;
            }
        }
        __stcs(&row[4096 + t], tp);
    }
}

// ---------------------------------------------------------------------------
// Launch (FROZEN R10 structure — best validated): pass chain recorded first,
// adj on a least-priority stream rooted at the fork, joined at the end.
// ---------------------------------------------------------------------------
extern "C" void kernel_launch(void* const* d_in, const int* in_sizes, int n_in,
                              void* d_out, int out_size)
{
    const float* x = nullptr; const int* cams = nullptr;
    const float* att_w = nullptr; const float* att_b = nullptr;
    const float* rmean = nullptr;

    for (int i = 0; i < n_in; ++i) {
        const int sz = in_sizes[i];
        if      (sz == BN * CN)           x = (const float*)d_in[i];
        else if (sz == BN)                cams = (const int*)d_in[i];
        else if (sz == LN * CN) { if (!att_w) att_w = (const float*)d_in[i];
                                  else        rmean = (const float*)d_in[i]; }
        else if (sz == LN)                att_b = (const float*)d_in[i];
    }

    float* out = (float*)d_out;

    static cudaStream_t s2 = nullptr;
    static cudaEvent_t evFork = nullptr, evJoin = nullptr;
    if (s2 == nullptr) {
        int loPri = 0, hiPri = 0;
        cudaDeviceGetStreamPriorityRange(&loPri, &hiPri);
        cudaStreamCreateWithPriority(&s2, cudaStreamNonBlocking, loPri);
        cudaEventCreateWithFlags(&evFork, cudaEventDisableTiming);
        cudaEventCreateWithFlags(&evJoin, cudaEventDisableTiming);
    }

    cudaEventRecord(evFork, 0);

    zero_kernel<<<48, 256>>>();
    pass_kernel<<<NPB, 256>>>(x, cams, att_w, att_b, out);
    tail_kernel<<<48, 256>>>(rmean, out);

    cudaStreamWaitEvent(s2, evFork, 0);
    adj_kernel<<<MN, 256, 0, s2>>>(out);
    cudaEventRecord(evJoin, s2);

    cudaStreamWaitEvent(0, evJoin, 0);
}

// round 16
// speedup vs baseline: 1.0911x; 1.0681x over previous
#include <cuda_runtime.h>
#include <cuda_bf16.h>
#include <math.h>

// Problem constants (fixed by the reference)
#define BN    8192
#define CN    2048
#define LN    6
#define HALF  4096
#define MN    (BN + LN)          // 8198
#define XOUT_ELEMS ((size_t)MN * CN)
#define ADJ_OFF    XOUT_ELEMS

#define G     4                  // rows staged per group (pass)
#define NGRP  16                 // groups per block (64 rows/block, grid 128)

// ---- scratch (no allocations allowed) ----
__device__ float g_U[LN * CN];   // sum_n s_n * x_n per cam
__device__ float g_denom[LN];    // per-cam sum of scores
__device__ float g_cnt[LN];      // per-cam counts

// ---------------------------------------------------------------------------
// 0) zero the scratch accumulators (graph replays reuse them)
// ---------------------------------------------------------------------------
__global__ void zero_kernel() {
    int idx = blockIdx.x * blockDim.x + threadIdx.x;
    if (idx < LN * CN) g_U[idx] = 0.0f;
    if (idx < LN) { g_denom[idx] = 0.0f; g_cnt[idx] = 0.0f; }
}

// ---------------------------------------------------------------------------
// 1) pass (BYTE-IDENTICAL to R8/R10 — best validated, 90.3us config):
//    group-staged score + copy + weighted accumulation.
// ---------------------------------------------------------------------------
__global__ void __launch_bounds__(256) pass_kernel(
    const float* __restrict__ x, const int* __restrict__ cams,
    const float* __restrict__ att_w, const float* __restrict__ att_b,
    float* __restrict__ out)
{
    __shared__ float sx[G][CN];      // 32 KB staged rows
    __shared__ float sscore[G];
    __shared__ int   scam[G];
    __shared__ float sden[LN];
    __shared__ float scnt[LN];

    const int t = threadIdx.x;
    const int w = t >> 5, lane = t & 31;
    if (t < LN) { sden[t] = 0.0f; scnt[t] = 0.0f; }

    float acc[LN][8];
#pragma unroll
    for (int l = 0; l < LN; ++l)
#pragma unroll
        for (int k = 0; k < 8; ++k) acc[l][k] = 0.0f;

    const int r0 = blockIdx.x * (G * NGRP);          // 64 rows per block
    const float4* __restrict__ x4 = (const float4*)x;
    const float4* __restrict__ w4 = (const float4*)att_w;
    float4* __restrict__ o4 = (float4*)out;

    float4 buf[8];
#pragma unroll
    for (int m = 0; m < 8; ++m) {
        const int f = t + 256 * m;
        buf[m] = x4[(size_t)(r0 + (f >> 9)) * 512 + (f & 511)];
    }

    for (int g = 0; g < NGRP; ++g) {
        const int rows = r0 + G * g;

        __syncthreads();

#pragma unroll
        for (int m = 0; m < 8; ++m) {
            const int f = t + 256 * m;
            const int rig = f >> 9, c4 = f & 511;
            *(float4*)&sx[rig][4 * c4] = buf[m];
            o4[(size_t)(rows + rig) * 512 + c4] = buf[m];
        }
        if (t < G) scam[t] = __ldg(&cams[rows + t]);
        __syncthreads();

        if (w < G) {
            const int cam = scam[w];
            float s = 0.0f;
#pragma unroll
            for (int k = 0; k < 16; ++k) {
                const int c4 = lane + 32 * k;
                const float4 xv = *(const float4*)&sx[w][4 * c4];
                const float4 wv = __ldg(&w4[(size_t)cam * 512 + c4]);
                s += xv.x * wv.x + xv.y * wv.y + xv.z * wv.z + xv.w * wv.w;
            }
#pragma unroll
            for (int o = 16; o > 0; o >>= 1) s += __shfl_down_sync(0xffffffffu, s, o);
            if (lane == 0) {
                s += __ldg(&att_b[cam]);
                sscore[w] = s;
                atomicAdd(&sden[cam], s);
                atomicAdd(&scnt[cam], 1.0f);
            }
        }
        __syncthreads();

        if (g + 1 < NGRP) {
#pragma unroll
            for (int m = 0; m < 8; ++m) {
                const int f = t + 256 * m;
                buf[m] = x4[(size_t)(rows + G + (f >> 9)) * 512 + (f & 511)];
            }
        }

#pragma unroll
        for (int r = 0; r < G; ++r) {
            const float s = sscore[r];
            const int cam = scam[r];
            const float4 xa = *(const float4*)&sx[r][4 * t];
            const float4 xb = *(const float4*)&sx[r][1024 + 4 * t];
#pragma unroll
            for (int l = 0; l < LN; ++l) {
                const float sl = (cam == l) ? s : 0.0f;
                acc[l][0] += sl * xa.x;  acc[l][1] += sl * xa.y;
                acc[l][2] += sl * xa.z;  acc[l][3] += sl * xa.w;
                acc[l][4] += sl * xb.x;  acc[l][5] += sl * xb.y;
                acc[l][6] += sl * xb.z;  acc[l][7] += sl * xb.w;
            }
        }
    }

#pragma unroll
    for (int l = 0; l < LN; ++l) {
#pragma unroll
        for (int k = 0; k < 4; ++k)
            atomicAdd(&g_U[l * CN + 4 * t + k], acc[l][k]);
#pragma unroll
        for (int k = 0; k < 4; ++k)
            atomicAdd(&g_U[l * CN + 1024 + 4 * t + k], acc[l][k + 4]);
    }
    if (t < LN) {
        atomicAdd(&g_denom[t], sden[t]);
        atomicAdd(&g_cnt[t],   scnt[t]);
    }
}

// ---------------------------------------------------------------------------
// 2) tail rows of x_out:  U/denom if cam present, else running_mean
// ---------------------------------------------------------------------------
__global__ void tail_kernel(const float* __restrict__ rmean,
                            float* __restrict__ out)
{
    int idx = blockIdx.x * blockDim.x + threadIdx.x;
    if (idx < LN * CN) {
        int l = idx >> 11;
        float v = (g_cnt[l] > 0.0f) ? (g_U[idx] / g_denom[l]) : __ldg(&rmean[idx]);
        out[(size_t)BN * CN + idx] = v;
    }
}

// ---------------------------------------------------------------------------
// 3) adj fill — ALIGNMENT-PERFECT rewrite.
//    A row PAIR (rows 2p, 2p+1) = 16396 floats = exactly 4099 float4s,
//    starting 16B-aligned (2p*8198 ≡ 0 mod 4). All class boundaries
//    (4096 / 8192 / 8196) are even, so both rows of a pair share one
//    (lo, hi, ta, tb) constant set. One block per pair, 17 aligned STG.128
//    per thread — warp stores are 512B sector-aligned (4 wavefronts/512B vs
//    3/256B before: 1.5x fewer L1 wavefronts per byte).
//    Pair-local float4 index q maps: q<1024 lo | q<2048 hi | 2048 ta |
//    2049 (tb,tb,lo,lo) | <3073 lo | 3073 (lo,lo,hi,hi) | <4097 hi |
//    4097 (hi,hi,ta,ta) | 4098 (ta,ta,tb,tb).
// ---------------------------------------------------------------------------
__global__ void __launch_bounds__(256) adj_kernel(float* __restrict__ out)
{
    const int p = blockIdx.x;                     // pair index: rows 2p, 2p+1
    const int t = threadIdx.x;

    const float DA = rsqrtf(4098.0f);   // rgb sample
    const float DB = rsqrtf(4100.0f);   // ir sample
    const float DC = rsqrtf(4097.0f);   // cam node

    float4* pr = (float4*)(out + ADJ_OFF + (size_t)p * 2 * MN);

    if (p < 4096) {
        // ---- sample pairs: segment-constant fill ----
        float lo, hi, ta, tb;
        if (p < 2048) { lo = DA * DA; hi = 0.0f;    ta = 0.0f;    tb = DA * DC; }
        else          { lo = 0.0f;    hi = DB * DB; ta = DB * DC; tb = 0.0f;    }

        const float4 LO4   = make_float4(lo, lo, lo, lo);
        const float4 HI4   = make_float4(hi, hi, hi, hi);
        const float4 TA4   = make_float4(ta, ta, ta, ta);
        const float4 Q2049 = make_float4(tb, tb, lo, lo);
        const float4 Q3073 = make_float4(lo, lo, hi, hi);
        const float4 Q4097 = make_float4(hi, hi, ta, ta);
        const float4 Q4098 = make_float4(ta, ta, tb, tb);

#pragma unroll
        for (int k = 0; k < 17; ++k) {
            const int q = t + 256 * k;
            if (q >= 4099) break;
            float4 v;
            if      (q < 1024)  v = LO4;
            else if (q < 2048)  v = HI4;
            else if (q == 2048) v = TA4;
            else if (q == 2049) v = Q2049;
            else if (q < 3073)  v = LO4;
            else if (q == 3073) v = Q3073;
            else if (q < 4097)  v = HI4;
            else if (q == 4097) v = Q4097;
            else                v = Q4098;
            __stcs(&pr[q], v);
        }
    } else {
        // ---- cam pairs (3 blocks): per-element generic fill ----
        const int rE = 2 * p;                     // 8192 / 8194 / 8196
        const float DCA = DC * DA, DCB = DC * DB, DC2 = DC * DC;
        for (int k = 0; k < 17; ++k) {
            const int q = t + 256 * k;
            if (q >= 4099) break;
            float vv[4];
#pragma unroll
            for (int j = 0; j < 4; ++j) {
                const int e = 4 * q + j;          // pair-local float index
                const int r = rE + (e >= MN ? 1 : 0);
                const int c = e - (e >= MN ? MN : 0);
                const bool rgbCam = (r < BN + 4);
                float v;
                if (c < HALF)      v = rgbCam ? 0.0f : DCA;
                else if (c < BN)   v = rgbCam ? DCB : 0.0f;
                else               v = (c == r) ? DC2 : 0.0f;
                vv[j] = v;
            }
            __stcs(&pr[q], make_float4(vv[0], vv[1], vv[2], vv[3]));
        }
    }
}

// ---------------------------------------------------------------------------
// Launch (FROZEN R10 structure — best validated): pass chain recorded first,
// adj on a least-priority stream rooted at the fork, joined at the end.
// ---------------------------------------------------------------------------
extern "C" void kernel_launch(void* const* d_in, const int* in_sizes, int n_in,
                              void* d_out, int out_size)
{
    const float* x = nullptr; const int* cams = nullptr;
    const float* att_w = nullptr; const float* att_b = nullptr;
    const float* rmean = nullptr;

    for (int i = 0; i < n_in; ++i) {
        const int sz = in_sizes[i];
        if      (sz == BN * CN)           x = (const float*)d_in[i];
        else if (sz == BN)                cams = (const int*)d_in[i];
        else if (sz == LN * CN) { if (!att_w) att_w = (const float*)d_in[i];
                                  else        rmean = (const float*)d_in[i]; }
        else if (sz == LN)                att_b = (const float*)d_in[i];
    }

    float* out = (float*)d_out;

    static cudaStream_t s2 = nullptr;
    static cudaEvent_t evFork = nullptr, evJoin = nullptr;
    if (s2 == nullptr) {
        int loPri = 0, hiPri = 0;
        cudaDeviceGetStreamPriorityRange(&loPri, &hiPri);
        cudaStreamCreateWithPriority(&s2, cudaStreamNonBlocking, loPri);
        cudaEventCreateWithFlags(&evFork, cudaEventDisableTiming);
        cudaEventCreateWithFlags(&evJoin, cudaEventDisableTiming);
    }

    cudaEventRecord(evFork, 0);

    zero_kernel<<<48, 256>>>();
    pass_kernel<<<128, 256>>>(x, cams, att_w, att_b, out);
    tail_kernel<<<48, 256>>>(rmean, out);

    cudaStreamWaitEvent(s2, evFork, 0);
    adj_kernel<<<4099, 256, 0, s2>>>(out);
    cudaEventRecord(evJoin, s2);

    cudaStreamWaitEvent(0, evJoin, 0);
}